// round 4
// baseline (speedup 1.0000x reference)
#include <cuda_runtime.h>
#include <cstddef>

#define Bsz 64
#define Sq  512
#define Isz 512
#define Hsz 1024
#define G3  3072   // 3*Hsz

// Scratch (static device allocations are allowed; no cudaMalloc anywhere)
__device__ float g_xg[(size_t)Sq * Bsz * G3];   // x_gates, layout [s][b][g], g in 0..3071 (r|z|n)
__device__ float g_h[2][Bsz * Hsz];             // h ping-pong buffers

// ---------------------------------------------------------------------------
// Kernel 1: x_gates = inputs @ W_ih^T + bias_ih
//   A: inputs as [M=B*S][K=I] row-major (row m = (b = m>>9, s = m&511))
//   W: weight_ih [G3][I] row-major
//   Output written to g_xg in [s][b][g] layout.
// 128x128 tile, BK=16, 256 threads, 8x8 register micro-tile.
// ---------------------------------------------------------------------------
__global__ __launch_bounds__(256) void xgemm_kernel(
    const float* __restrict__ A,
    const float* __restrict__ W,
    const float* __restrict__ bias,
    float* __restrict__ xg)
{
    __shared__ float As[16][132];   // [k][m], padded
    __shared__ float Bs[16][132];   // [k][n], padded

    const int m0 = blockIdx.y * 128;
    const int n0 = blockIdx.x * 128;
    const int t  = threadIdx.x;
    const int tr = t >> 4;          // 0..15
    const int tc = t & 15;          // 0..15

    const int lrow = t >> 2;        // 0..63
    const int lk4  = (t & 3) * 4;   // 0,4,8,12

    float acc[8][8] = {};

    for (int k0 = 0; k0 < Isz; k0 += 16) {
        #pragma unroll
        for (int p = 0; p < 2; p++) {
            int mm = lrow + p * 64;
            float4 va = *(const float4*)(A + (size_t)(m0 + mm) * Isz + k0 + lk4);
            As[lk4 + 0][mm] = va.x; As[lk4 + 1][mm] = va.y;
            As[lk4 + 2][mm] = va.z; As[lk4 + 3][mm] = va.w;
            float4 vw = *(const float4*)(W + (size_t)(n0 + mm) * Isz + k0 + lk4);
            Bs[lk4 + 0][mm] = vw.x; Bs[lk4 + 1][mm] = vw.y;
            Bs[lk4 + 2][mm] = vw.z; Bs[lk4 + 3][mm] = vw.w;
        }
        __syncthreads();

        #pragma unroll
        for (int kk = 0; kk < 16; kk++) {
            float a[8], b[8];
            #pragma unroll
            for (int i = 0; i < 8; i++) a[i] = As[kk][tr * 8 + i];
            #pragma unroll
            for (int j = 0; j < 8; j++) b[j] = Bs[kk][tc * 8 + j];
            #pragma unroll
            for (int i = 0; i < 8; i++)
                #pragma unroll
                for (int j = 0; j < 8; j++)
                    acc[i][j] += a[i] * b[j];
        }
        __syncthreads();
    }

    // Epilogue: add bias, scatter to [s][b][g]
    float bv[8];
    #pragma unroll
    for (int j = 0; j < 8; j++) bv[j] = bias[n0 + tc * 8 + j];

    #pragma unroll
    for (int i = 0; i < 8; i++) {
        int m = m0 + tr * 8 + i;
        int s = m & (Sq - 1);
        int b = m >> 9;
        float* dst = xg + (size_t)s * (Bsz * G3) + (size_t)b * G3 + n0 + tc * 8;
        #pragma unroll
        for (int j = 0; j < 8; j++) dst[j] = acc[i][j] + bv[j];
    }
}

// ---------------------------------------------------------------------------
// Kernel 2: one fused GRU step.
//   r = sigmoid(xr + h@Whr^T + bhr)
//   z = sigmoid(xz + h@Whz^T + bhz)
//   n = tanh  (xn + r*(h@Whn^T + bhn))
//   h' = (1-z)*n + z*h
// Grid: 128 blocks (8 hidden columns each, all 64 batches, all 3 gates).
// 128 threads: thread = (b-group of 4) x (one j). 12 fp32 accumulators.
// ---------------------------------------------------------------------------
__global__ __launch_bounds__(128) void gru_step_kernel(
    const float* __restrict__ xg_s,   // [B][G3] for this step
    const float* __restrict__ h_in,   // [B][H]
    const float* __restrict__ Whh,    // [G3][H] row-major
    const float* __restrict__ bhh,    // [G3]
    float* __restrict__ h_out,        // [B][H]
    float* __restrict__ out_s)        // out + s*H; element (b,j) at b*S*H + j
{
    __shared__ float hs[64][65];      // [b][k-tile], padded (conflict-free inner reads)
    __shared__ float ws[24][65];      // rows: [g*8 + jj][k-tile]

    const int t  = threadIdx.x;
    const int j0 = blockIdx.x * 8;
    const int jj = t & 7;
    const int b0 = (t >> 3) * 4;      // 16 b-groups of 4

    float ar[4] = {}, az[4] = {}, an[4] = {};

    for (int k0 = 0; k0 < Hsz; k0 += 64) {
        // Load h tile: 64 x 64
        #pragma unroll
        for (int i = 0; i < 32; i++) {
            int idx = t + 128 * i;
            int k = idx & 63, b = idx >> 6;
            hs[b][k] = h_in[b * Hsz + k0 + k];
        }
        // Load W tile: 24 rows (3 gates x 8 j) x 64
        #pragma unroll
        for (int i = 0; i < 12; i++) {
            int idx = t + 128 * i;
            int k = idx & 63, row = idx >> 6;          // 0..23
            int g = row >> 3, jr = row & 7;
            ws[row][k] = Whh[(size_t)(g * Hsz + j0 + jr) * Hsz + k0 + k];
        }
        __syncthreads();

        #pragma unroll 8
        for (int kk = 0; kk < 64; kk++) {
            float wr = ws[jj][kk];
            float wz = ws[8  + jj][kk];
            float wn = ws[16 + jj][kk];
            #pragma unroll
            for (int i = 0; i < 4; i++) {
                float hv = hs[b0 + i][kk];
                ar[i] += hv * wr;
                az[i] += hv * wz;
                an[i] += hv * wn;
            }
        }
        __syncthreads();
    }

    const int j = j0 + jj;
    const float bhr = bhh[j];
    const float bhz = bhh[Hsz + j];
    const float bhn = bhh[2 * Hsz + j];

    #pragma unroll
    for (int i = 0; i < 4; i++) {
        int b = b0 + i;
        float xr = xg_s[(size_t)b * G3 + j];
        float xz = xg_s[(size_t)b * G3 + Hsz + j];
        float xn = xg_s[(size_t)b * G3 + 2 * Hsz + j];
        float hp = h_in[b * Hsz + j];

        float r = 1.f / (1.f + expf(-(xr + ar[i] + bhr)));
        float z = 1.f / (1.f + expf(-(xz + az[i] + bhz)));
        float n = tanhf(xn + r * (an[i] + bhn));
        float hn = (1.f - z) * n + z * hp;

        h_out[b * Hsz + j] = hn;
        out_s[(size_t)b * Sq * Hsz + j] = hn;
    }
}

// ---------------------------------------------------------------------------
// kernel_launch: graph-capturable (kernel launches + one async D2D memcpy).
// Inputs: 0 inputs[B,S,I], 1 h0[1,B,H], 2 weight_ih[3H,I], 3 weight_hh[3H,H],
//         4 bias_ih[3H], 5 bias_hh[3H].  Output: outputs[B,S,H] ++ hn[1,B,H].
// ---------------------------------------------------------------------------
extern "C" void kernel_launch(void* const* d_in, const int* in_sizes, int n_in,
                              void* d_out, int out_size)
{
    const float* inputs = (const float*)d_in[0];
    const float* h0     = (const float*)d_in[1];
    const float* Wih    = (const float*)d_in[2];
    const float* Whh    = (const float*)d_in[3];
    const float* bih    = (const float*)d_in[4];
    const float* bhh    = (const float*)d_in[5];
    float* out = (float*)d_out;

    float* xg   = nullptr;
    float* hbuf = nullptr;
    cudaGetSymbolAddress((void**)&xg, g_xg);
    cudaGetSymbolAddress((void**)&hbuf, g_h);

    // Phase A: all input projections in one GEMM
    dim3 ggrid(G3 / 128, (Bsz * Sq) / 128);   // (24, 256)
    xgemm_kernel<<<ggrid, 256>>>(inputs, Wih, bih, xg);

    // Phase B: sequential scan, one fused kernel per step
    for (int s = 0; s < Sq; s++) {
        const float* h_in = (s == 0) ? h0 : (hbuf + (size_t)(s & 1) * Bsz * Hsz);
        float* h_out = hbuf + (size_t)((s + 1) & 1) * Bsz * Hsz;
        gru_step_kernel<<<Hsz / 8, 128>>>(
            xg + (size_t)s * Bsz * G3,
            h_in, Whh, bhh, h_out,
            out + (size_t)s * Hsz);
    }

    // hn = final h (after step 511 it lives in buffer ((511+1)&1) = 0)
    cudaMemcpyAsync(out + (size_t)Bsz * Sq * Hsz, hbuf,
                    (size_t)Bsz * Hsz * sizeof(float),
                    cudaMemcpyDeviceToDevice);
}

// round 5
// speedup vs baseline: 1.4818x; 1.4818x over previous
#include <cuda_runtime.h>
#include <cstddef>

#define Bsz 64
#define Sq  512
#define Isz 512
#define Hsz 1024
#define G3  3072   // 3*Hsz

// Scratch (static device allocations; no cudaMalloc anywhere)
__device__ float g_xg[(size_t)Sq * Bsz * G3];   // x_gates, layout [s][b][g]
__device__ float g_h[2][Bsz * Hsz];             // h ping-pong

// ---------------------------------------------------------------------------
// Kernel 1: x_gates = inputs @ W_ih^T + bias_ih   (unchanged — near fp32 roofline)
// ---------------------------------------------------------------------------
__global__ __launch_bounds__(256) void xgemm_kernel(
    const float* __restrict__ A,
    const float* __restrict__ W,
    const float* __restrict__ bias,
    float* __restrict__ xg)
{
    __shared__ float As[16][132];
    __shared__ float Bs[16][132];

    const int m0 = blockIdx.y * 128;
    const int n0 = blockIdx.x * 128;
    const int t  = threadIdx.x;
    const int tr = t >> 4;
    const int tc = t & 15;

    const int lrow = t >> 2;
    const int lk4  = (t & 3) * 4;

    float acc[8][8] = {};

    for (int k0 = 0; k0 < Isz; k0 += 16) {
        #pragma unroll
        for (int p = 0; p < 2; p++) {
            int mm = lrow + p * 64;
            float4 va = *(const float4*)(A + (size_t)(m0 + mm) * Isz + k0 + lk4);
            As[lk4 + 0][mm] = va.x; As[lk4 + 1][mm] = va.y;
            As[lk4 + 2][mm] = va.z; As[lk4 + 3][mm] = va.w;
            float4 vw = *(const float4*)(W + (size_t)(n0 + mm) * Isz + k0 + lk4);
            Bs[lk4 + 0][mm] = vw.x; Bs[lk4 + 1][mm] = vw.y;
            Bs[lk4 + 2][mm] = vw.z; Bs[lk4 + 3][mm] = vw.w;
        }
        __syncthreads();

        #pragma unroll
        for (int kk = 0; kk < 16; kk++) {
            float a[8], b[8];
            #pragma unroll
            for (int i = 0; i < 8; i++) a[i] = As[kk][tr * 8 + i];
            #pragma unroll
            for (int j = 0; j < 8; j++) b[j] = Bs[kk][tc * 8 + j];
            #pragma unroll
            for (int i = 0; i < 8; i++)
                #pragma unroll
                for (int j = 0; j < 8; j++)
                    acc[i][j] += a[i] * b[j];
        }
        __syncthreads();
    }

    float bv[8];
    #pragma unroll
    for (int j = 0; j < 8; j++) bv[j] = bias[n0 + tc * 8 + j];

    #pragma unroll
    for (int i = 0; i < 8; i++) {
        int m = m0 + tr * 8 + i;
        int s = m & (Sq - 1);
        int b = m >> 9;
        float* dst = xg + (size_t)s * (Bsz * G3) + (size_t)b * G3 + n0 + tc * 8;
        #pragma unroll
        for (int j = 0; j < 8; j++) dst[j] = acc[i][j] + bv[j];
    }
}

// ---------------------------------------------------------------------------
// Kernel 2: one fused GRU step, restructured for FMA-pipe saturation.
//
// Block: j-tile of 8 columns (x3 gates) x all 64 batches = 1536 outputs.
// 256 threads = 2 k-groups of 128; group g covers K range [g*512,(g+1)*512).
// Thread tile: 4 batches x 1 j x 3 gates = 12 accumulators.
// smem: h tile transposed to [k][b] so 4 batches load as one LDS.128;
//       W rows read 4 k's per LDS.128.  Inner 4-k block: 7 LDS.128 / 48 FFMA.
// Global->smem window loads are double-buffered through registers.
// Cross-group reduction in smem, then fused pointwise epilogue.
// ---------------------------------------------------------------------------
#define KCH 512   // k per group
#define WIN 64    // k per window
#define NW  (KCH / WIN)
#define HSTR 68   // padded stride (multiple of 4 floats -> float4-aligned rows)

__global__ __launch_bounds__(256) void gru_step_kernel(
    const float* __restrict__ xg_s,   // [B][G3] for this step
    const float* __restrict__ h_in,   // [B][H]
    const float* __restrict__ Whh,    // [G3][H]
    const float* __restrict__ bhh,    // [G3]
    float* __restrict__ h_out,        // [B][H]
    float* __restrict__ out_s)        // out + s*H; element (b,j) at b*S*H + j
{
    // pool: hs[2][64][HSTR] then ws[2][24][HSTR]; reused as reduction buffer.
    __shared__ __align__(16) float pool[2 * 64 * HSTR + 2 * 24 * HSTR];

    const int t  = threadIdx.x;
    const int g  = t >> 7;          // k-group 0/1
    const int lt = t & 127;

    float* hsg = pool + g * (64 * HSTR);
    float* wsg = pool + 2 * 64 * HSTR + g * (24 * HSTR);

    const int j0 = blockIdx.x * 8;
    const int jj = lt & 7;
    const int b0 = (lt >> 3) * 4;   // 16 groups of 4 batches

    const int kbase = g * KCH;

    // loader mapping: h tile is 64 b x 64 k; thread owns batch hb, half-k hk
    const int hb = lt & 63;
    const int hk = (lt >> 6) * 32;

    float4 hreg[8];
    float4 wreg[3];
    int wrow[3], wkq[3];
    #pragma unroll
    for (int i = 0; i < 3; i++) {
        int F = lt + 128 * i;               // 0..383 float4 slots
        int r = F >> 4;                     // 0..23 : gate*8 + jr
        wrow[i] = r;
        wkq[i]  = (F & 15) * 4;
    }

    // prefetch window 0
    {
        const float* hp = h_in + (size_t)hb * Hsz + kbase + hk;
        #pragma unroll
        for (int i = 0; i < 8; i++) hreg[i] = *(const float4*)(hp + i * 4);
        #pragma unroll
        for (int i = 0; i < 3; i++) {
            int gate = wrow[i] >> 3, jr = wrow[i] & 7;
            wreg[i] = *(const float4*)(Whh + (size_t)(gate * Hsz + j0 + jr) * Hsz
                                           + kbase + wkq[i]);
        }
    }

    float ar[4] = {}, az[4] = {}, an[4] = {};

    for (int w = 0; w < NW; w++) {
        __syncthreads();   // prior window's tiles fully consumed

        // store prefetched window into smem (h transposed to [k][b])
        #pragma unroll
        for (int i = 0; i < 8; i++) {
            int k = hk + i * 4;
            hsg[(k + 0) * HSTR + hb] = hreg[i].x;
            hsg[(k + 1) * HSTR + hb] = hreg[i].y;
            hsg[(k + 2) * HSTR + hb] = hreg[i].z;
            hsg[(k + 3) * HSTR + hb] = hreg[i].w;
        }
        #pragma unroll
        for (int i = 0; i < 3; i++)
            *(float4*)&wsg[wrow[i] * HSTR + wkq[i]] = wreg[i];

        __syncthreads();

        // prefetch next window while computing this one
        if (w + 1 < NW) {
            int kb = kbase + (w + 1) * WIN;
            const float* hp = h_in + (size_t)hb * Hsz + kb + hk;
            #pragma unroll
            for (int i = 0; i < 8; i++) hreg[i] = *(const float4*)(hp + i * 4);
            #pragma unroll
            for (int i = 0; i < 3; i++) {
                int gate = wrow[i] >> 3, jr = wrow[i] & 7;
                wreg[i] = *(const float4*)(Whh + (size_t)(gate * Hsz + j0 + jr) * Hsz
                                               + kb + wkq[i]);
            }
        }

        // compute: 64 k's, 4 at a time
        #pragma unroll
        for (int kk = 0; kk < WIN; kk += 4) {
            float4 wr4 = *(const float4*)&wsg[jj * HSTR + kk];
            float4 wz4 = *(const float4*)&wsg[(8 + jj) * HSTR + kk];
            float4 wn4 = *(const float4*)&wsg[(16 + jj) * HSTR + kk];
            float wrA[4] = {wr4.x, wr4.y, wr4.z, wr4.w};
            float wzA[4] = {wz4.x, wz4.y, wz4.z, wz4.w};
            float wnA[4] = {wn4.x, wn4.y, wn4.z, wn4.w};
            #pragma unroll
            for (int u = 0; u < 4; u++) {
                float4 h4 = *(const float4*)&hsg[(kk + u) * HSTR + b0];
                float hv[4] = {h4.x, h4.y, h4.z, h4.w};
                #pragma unroll
                for (int i = 0; i < 4; i++) {
                    ar[i] += hv[i] * wrA[u];
                    az[i] += hv[i] * wzA[u];
                    an[i] += hv[i] * wnA[u];
                }
            }
        }
    }

    // cross-group reduction (pad 13 -> conflict-free)
    __syncthreads();
    float* red = pool;
    if (g == 1) {
        #pragma unroll
        for (int i = 0; i < 4; i++) {
            red[lt * 13 + i]     = ar[i];
            red[lt * 13 + 4 + i] = az[i];
            red[lt * 13 + 8 + i] = an[i];
        }
    }
    __syncthreads();

    if (g == 0) {
        #pragma unroll
        for (int i = 0; i < 4; i++) {
            ar[i] += red[lt * 13 + i];
            az[i] += red[lt * 13 + 4 + i];
            an[i] += red[lt * 13 + 8 + i];
        }

        const int j = j0 + jj;
        const float bhr = bhh[j];
        const float bhz = bhh[Hsz + j];
        const float bhn = bhh[2 * Hsz + j];

        #pragma unroll
        for (int i = 0; i < 4; i++) {
            int b = b0 + i;
            float xr = xg_s[(size_t)b * G3 + j];
            float xz = xg_s[(size_t)b * G3 + Hsz + j];
            float xn = xg_s[(size_t)b * G3 + 2 * Hsz + j];
            float hp = h_in[(size_t)b * Hsz + j];

            float r = 1.f / (1.f + expf(-(xr + ar[i] + bhr)));
            float z = 1.f / (1.f + expf(-(xz + az[i] + bhz)));
            float n = tanhf(xn + r * (an[i] + bhn));
            float hn = (1.f - z) * n + z * hp;

            h_out[(size_t)b * Hsz + j] = hn;
            out_s[(size_t)b * Sq * Hsz + j] = hn;
        }
    }
}

// ---------------------------------------------------------------------------
// kernel_launch (graph-capturable: kernels + one async D2D memcpy)
// ---------------------------------------------------------------------------
extern "C" void kernel_launch(void* const* d_in, const int* in_sizes, int n_in,
                              void* d_out, int out_size)
{
    const float* inputs = (const float*)d_in[0];
    const float* h0     = (const float*)d_in[1];
    const float* Wih    = (const float*)d_in[2];
    const float* Whh    = (const float*)d_in[3];
    const float* bih    = (const float*)d_in[4];
    const float* bhh    = (const float*)d_in[5];
    float* out = (float*)d_out;

    float* xg   = nullptr;
    float* hbuf = nullptr;
    cudaGetSymbolAddress((void**)&xg, g_xg);
    cudaGetSymbolAddress((void**)&hbuf, g_h);

    // Phase A: all input projections in one GEMM
    dim3 ggrid(G3 / 128, (Bsz * Sq) / 128);   // (24, 256)
    xgemm_kernel<<<ggrid, 256>>>(inputs, Wih, bih, xg);

    // Phase B: sequential scan, one fused kernel per step
    for (int s = 0; s < Sq; s++) {
        const float* h_in = (s == 0) ? h0 : (hbuf + (size_t)(s & 1) * Bsz * Hsz);
        float* h_out = hbuf + (size_t)((s + 1) & 1) * Bsz * Hsz;
        gru_step_kernel<<<Hsz / 8, 256>>>(
            xg + (size_t)s * Bsz * G3,
            h_in, Whh, bhh, h_out,
            out + (size_t)s * Hsz);
    }

    // hn = final h (buffer index ((511+1)&1) = 0)
    cudaMemcpyAsync(out + (size_t)Bsz * Sq * Hsz, hbuf,
                    (size_t)Bsz * Hsz * sizeof(float),
                    cudaMemcpyDeviceToDevice);
}

// round 6
// speedup vs baseline: 1.6686x; 1.1261x over previous
#include <cuda_runtime.h>
#include <cstddef>
#include <cstdint>

#define Bsz 64
#define Sq  512
#define Isz 512
#define Hsz 1024
#define G3  3072   // 3*Hsz

// Scratch (static device allocations; no cudaMalloc anywhere)
__device__ float g_xg[(size_t)Sq * Bsz * G3];   // x_gates, layout [s][b][g]
__device__ float g_hT[2][Hsz * Bsz];            // h TRANSPOSED [j][b], ping-pong

// ---------------------------------------------------------------------------
// Kernel 1: x_gates = inputs @ W_ih^T + bias_ih  (near fp32 roofline, unchanged)
// ---------------------------------------------------------------------------
__global__ __launch_bounds__(256) void xgemm_kernel(
    const float* __restrict__ A,
    const float* __restrict__ W,
    const float* __restrict__ bias,
    float* __restrict__ xg)
{
    __shared__ float As[16][132];
    __shared__ float Bs[16][132];

    const int m0 = blockIdx.y * 128;
    const int n0 = blockIdx.x * 128;
    const int t  = threadIdx.x;
    const int tr = t >> 4;
    const int tc = t & 15;
    const int lrow = t >> 2;
    const int lk4  = (t & 3) * 4;

    float acc[8][8] = {};

    for (int k0 = 0; k0 < Isz; k0 += 16) {
        #pragma unroll
        for (int p = 0; p < 2; p++) {
            int mm = lrow + p * 64;
            float4 va = *(const float4*)(A + (size_t)(m0 + mm) * Isz + k0 + lk4);
            As[lk4 + 0][mm] = va.x; As[lk4 + 1][mm] = va.y;
            As[lk4 + 2][mm] = va.z; As[lk4 + 3][mm] = va.w;
            float4 vw = *(const float4*)(W + (size_t)(n0 + mm) * Isz + k0 + lk4);
            Bs[lk4 + 0][mm] = vw.x; Bs[lk4 + 1][mm] = vw.y;
            Bs[lk4 + 2][mm] = vw.z; Bs[lk4 + 3][mm] = vw.w;
        }
        __syncthreads();

        #pragma unroll
        for (int kk = 0; kk < 16; kk++) {
            float a[8], b[8];
            #pragma unroll
            for (int i = 0; i < 8; i++) a[i] = As[kk][tr * 8 + i];
            #pragma unroll
            for (int j = 0; j < 8; j++) b[j] = Bs[kk][tc * 8 + j];
            #pragma unroll
            for (int i = 0; i < 8; i++)
                #pragma unroll
                for (int j = 0; j < 8; j++)
                    acc[i][j] += a[i] * b[j];
        }
        __syncthreads();
    }

    float bv[8];
    #pragma unroll
    for (int j = 0; j < 8; j++) bv[j] = bias[n0 + tc * 8 + j];

    #pragma unroll
    for (int i = 0; i < 8; i++) {
        int m = m0 + tr * 8 + i;
        int s = m & (Sq - 1);
        int b = m >> 9;
        float* dst = xg + (size_t)s * (Bsz * G3) + (size_t)b * G3 + n0 + tc * 8;
        #pragma unroll
        for (int j = 0; j < 8; j++) dst[j] = acc[i][j] + bv[j];
    }
}

// ---------------------------------------------------------------------------
// h0 [b][j] -> hT [j][b]   (once)
// ---------------------------------------------------------------------------
__global__ void h0_transpose_kernel(const float* __restrict__ h0,
                                    float* __restrict__ hT)
{
    int idx = blockIdx.x * blockDim.x + threadIdx.x;   // 65536 elements
    int j = idx >> 6, b = idx & 63;
    hT[idx] = h0[(size_t)b * Hsz + j];
}

// hT [j][b] -> dst [b][j]  (once, for hn)
__global__ void hT_untranspose_kernel(const float* __restrict__ hT,
                                      float* __restrict__ dst)
{
    int idx = blockIdx.x * blockDim.x + threadIdx.x;
    int b = idx >> 10, j = idx & 1023;
    dst[idx] = hT[(size_t)j * Bsz + b];
}

// ---------------------------------------------------------------------------
// Kernel 2: fused GRU step.
//
// Grid 128 blocks (j-tile 8), 256 threads = 4 k-chunks x 64 threads.
// Thread tile: 4 batches x 2 j x 3 gates = 24 accumulators (1.67 B/FMA).
// h is kept transposed [k][b] in gmem: staging = pure cp.async float4 copies,
// double-buffered windows of 64 k. Cross-chunk tree reduction in smem, then
// fused pointwise epilogue; h_out written transposed via STG.128.
// ---------------------------------------------------------------------------
#define WSTR  68                    // padded W row stride (floats)
#define HW    64                    // window size in k
#define KCH   256                   // k per chunk
#define NWIN  (KCH / HW)            // 4
#define NCH   4
#define HSG_F (HW * 64)             // 4096 floats: h window [k][b]
#define WSG_F (24 * WSTR)           // 1632 floats: W window [24 rows][k]
#define CHUNK_F (HSG_F + WSG_F)     // 5728
#define BUF_F  (NCH * CHUNK_F)      // 22912
#define SMEM_BYTES (2 * BUF_F * 4)  // 183296

__device__ __forceinline__ void cpa16(float* sp, const float* gp) {
    uint32_t sa = (uint32_t)__cvta_generic_to_shared(sp);
    asm volatile("cp.async.cg.shared.global [%0], [%1], 16;\n" :: "r"(sa), "l"(gp));
}

extern __shared__ float smem_pool[];

__global__ __launch_bounds__(256, 1) void gru_step_kernel(
    const float* __restrict__ xg_s,   // [B][G3] for this step
    const float* __restrict__ hT_in,  // [H][B] transposed
    const float* __restrict__ Whh,    // [G3][H]
    const float* __restrict__ bhh,    // [G3]
    float* __restrict__ hT_out,       // [H][B] transposed
    float* __restrict__ out_s)        // out + s*H; element (b,j) at b*S*H + j
{
    const int t  = threadIdx.x;
    const int c  = t >> 6;            // k-chunk 0..3
    const int lt = t & 63;
    const int j0 = blockIdx.x * 8;
    const int kc = c * KCH;

    // --- staging assignments (per chunk, 64 threads) ---
    // h: thread stages k-row lt of each window (16 float4, contiguous)
    // W: 6 float4 per thread over 24 rows x 16 float4
    const float* wgp[6];
    int wsoff[6];
    #pragma unroll
    for (int i = 0; i < 6; i++) {
        int f = lt + 64 * i;
        int r = f >> 4;                // 0..23  (gate*8 + jr)
        int kq = (f & 15) * 4;
        int gate = r >> 3, jr = r & 7;
        wgp[i]   = Whh + (size_t)(gate * Hsz + j0 + jr) * Hsz + kc + kq;
        wsoff[i] = r * WSTR + kq;
    }
    const float* hgp = hT_in + (size_t)(kc + lt) * Bsz;

    float* bufc[2];
    bufc[0] = smem_pool + c * CHUNK_F;
    bufc[1] = smem_pool + BUF_F + c * CHUNK_F;

    auto stage = [&](int w, int bsel) {
        float* hs = bufc[bsel];
        float* ws = bufc[bsel] + HSG_F;
        const float* hp = hgp + (size_t)w * HW * Bsz;
        float* hd = hs + lt * 64;
        #pragma unroll
        for (int i = 0; i < 16; i++)
            cpa16(hd + i * 4, hp + i * 4);
        #pragma unroll
        for (int i = 0; i < 6; i++)
            cpa16(ws + wsoff[i], wgp[i] + w * HW);
        asm volatile("cp.async.commit_group;\n" ::: "memory");
    };

    // --- compute mapping ---
    const int jj2 = lt >> 4;          // j-pair 0..3
    const int b0  = (lt & 15) * 4;    // batch group base

    float acc[2][3][4] = {};          // [jp][gate(r,z,n)][i]

    stage(0, 0);

    #pragma unroll
    for (int w = 0; w < NWIN; w++) {
        if (w + 1 < NWIN) {
            stage(w + 1, (w + 1) & 1);
            asm volatile("cp.async.wait_group 1;\n" ::: "memory");
        } else {
            asm volatile("cp.async.wait_group 0;\n" ::: "memory");
        }
        __syncthreads();

        const float* hs = bufc[w & 1];
        const float* ws = bufc[w & 1] + HSG_F;

        #pragma unroll
        for (int kk = 0; kk < HW; kk += 4) {
            float wr[2][4], wz[2][4], wn[2][4];
            #pragma unroll
            for (int jp = 0; jp < 2; jp++) {
                int rr = jj2 * 2 + jp;
                float4 a = *(const float4*)&ws[rr * WSTR + kk];
                float4 b = *(const float4*)&ws[(8 + rr) * WSTR + kk];
                float4 d = *(const float4*)&ws[(16 + rr) * WSTR + kk];
                wr[jp][0] = a.x; wr[jp][1] = a.y; wr[jp][2] = a.z; wr[jp][3] = a.w;
                wz[jp][0] = b.x; wz[jp][1] = b.y; wz[jp][2] = b.z; wz[jp][3] = b.w;
                wn[jp][0] = d.x; wn[jp][1] = d.y; wn[jp][2] = d.z; wn[jp][3] = d.w;
            }
            #pragma unroll
            for (int u = 0; u < 4; u++) {
                float4 h4 = *(const float4*)&hs[(kk + u) * 64 + b0];
                float hv[4] = {h4.x, h4.y, h4.z, h4.w};
                #pragma unroll
                for (int jp = 0; jp < 2; jp++)
                    #pragma unroll
                    for (int i = 0; i < 4; i++) {
                        acc[jp][0][i] += hv[i] * wr[jp][u];
                        acc[jp][1][i] += hv[i] * wz[jp][u];
                        acc[jp][2][i] += hv[i] * wn[jp][u];
                    }
            }
        }
        __syncthreads();   // buffer (w&1) free for stage(w+2)
    }

    // --- cross-chunk tree reduction (reuse pool) ---
    float* red = smem_pool;
    if (c >= 2) {
        float* d = red + ((c - 2) * 64 + lt) * 24;
        #pragma unroll
        for (int jp = 0; jp < 2; jp++)
            #pragma unroll
            for (int g = 0; g < 3; g++)
                #pragma unroll
                for (int i = 0; i < 4; i++)
                    d[jp * 12 + g * 4 + i] = acc[jp][g][i];
    }
    __syncthreads();
    if (c < 2) {
        const float* s = red + (c * 64 + lt) * 24;
        #pragma unroll
        for (int jp = 0; jp < 2; jp++)
            #pragma unroll
            for (int g = 0; g < 3; g++)
                #pragma unroll
                for (int i = 0; i < 4; i++)
                    acc[jp][g][i] += s[jp * 12 + g * 4 + i];
    }
    __syncthreads();
    if (c == 1) {
        float* d = red + lt * 24;
        #pragma unroll
        for (int jp = 0; jp < 2; jp++)
            #pragma unroll
            for (int g = 0; g < 3; g++)
                #pragma unroll
                for (int i = 0; i < 4; i++)
                    d[jp * 12 + g * 4 + i] = acc[jp][g][i];
    }
    __syncthreads();

    if (c == 0) {
        const float* s = red + lt * 24;
        #pragma unroll
        for (int jp = 0; jp < 2; jp++)
            #pragma unroll
            for (int g = 0; g < 3; g++)
                #pragma unroll
                for (int i = 0; i < 4; i++)
                    acc[jp][g][i] += s[jp * 12 + g * 4 + i];

        // --- fused pointwise epilogue ---
        #pragma unroll
        for (int jp = 0; jp < 2; jp++) {
            int j = j0 + jj2 * 2 + jp;
            float bhr = bhh[j];
            float bhz = bhh[Hsz + j];
            float bhn = bhh[2 * Hsz + j];
            float4 hp4 = *(const float4*)&hT_in[(size_t)j * Bsz + b0];
            float hpv[4] = {hp4.x, hp4.y, hp4.z, hp4.w};
            float hnv[4];
            #pragma unroll
            for (int i = 0; i < 4; i++) {
                int b = b0 + i;
                float xr = xg_s[(size_t)b * G3 + j];
                float xz = xg_s[(size_t)b * G3 + Hsz + j];
                float xn = xg_s[(size_t)b * G3 + 2 * Hsz + j];
                float r = 1.f / (1.f + expf(-(xr + acc[jp][0][i] + bhr)));
                float z = 1.f / (1.f + expf(-(xz + acc[jp][1][i] + bhz)));
                float n = tanhf(xn + r * (acc[jp][2][i] + bhn));
                hnv[i] = (1.f - z) * n + z * hpv[i];
                out_s[(size_t)b * Sq * Hsz + j] = hnv[i];
            }
            *(float4*)&hT_out[(size_t)j * Bsz + b0] =
                make_float4(hnv[0], hnv[1], hnv[2], hnv[3]);
        }
    }
}

// ---------------------------------------------------------------------------
// kernel_launch (graph-capturable: kernels only)
// ---------------------------------------------------------------------------
extern "C" void kernel_launch(void* const* d_in, const int* in_sizes, int n_in,
                              void* d_out, int out_size)
{
    const float* inputs = (const float*)d_in[0];
    const float* h0     = (const float*)d_in[1];
    const float* Wih    = (const float*)d_in[2];
    const float* Whh    = (const float*)d_in[3];
    const float* bih    = (const float*)d_in[4];
    const float* bhh    = (const float*)d_in[5];
    float* out = (float*)d_out;

    float* xg  = nullptr;
    float* hT  = nullptr;
    cudaGetSymbolAddress((void**)&xg, g_xg);
    cudaGetSymbolAddress((void**)&hT, g_hT);

    cudaFuncSetAttribute(gru_step_kernel,
                         cudaFuncAttributeMaxDynamicSharedMemorySize, SMEM_BYTES);

    // Phase A: input projections (one GEMM) + h0 transpose
    dim3 ggrid(G3 / 128, (Bsz * Sq) / 128);   // (24, 256)
    xgemm_kernel<<<ggrid, 256>>>(inputs, Wih, bih, xg);
    h0_transpose_kernel<<<(Hsz * Bsz) / 256, 256>>>(h0, hT);

    // Phase B: sequential scan
    for (int s = 0; s < Sq; s++) {
        const float* hin = hT + (size_t)(s & 1) * Hsz * Bsz;
        float* hout      = hT + (size_t)((s + 1) & 1) * Hsz * Bsz;
        gru_step_kernel<<<Hsz / 8, 256, SMEM_BYTES>>>(
            xg + (size_t)s * Bsz * G3,
            hin, Whh, bhh, hout,
            out + (size_t)s * Hsz);
    }

    // hn: final h is in buffer ((511+1)&1) = 0, transposed -> untranspose
    hT_untranspose_kernel<<<(Hsz * Bsz) / 256, 256>>>(
        hT, out + (size_t)Bsz * Sq * Hsz);
}

// round 7
// speedup vs baseline: 1.7580x; 1.0536x over previous
#include <cuda_runtime.h>
#include <cstddef>
#include <cstdint>

#define Bsz 64
#define Sq  512
#define Isz 512
#define Hsz 1024
#define G3  3072   // 3*Hsz

// Scratch (static device allocations; no cudaMalloc anywhere)
__device__ float g_xg[(size_t)Sq * Bsz * G3];   // x_gates, layout [s][b][g]
__device__ float g_hT[2][Hsz * Bsz];            // h TRANSPOSED [j][b], ping-pong
__device__ unsigned g_bar_count;                // grid barrier arrivals (self-resets)
__device__ unsigned g_bar_phase;                // grid barrier phase (monotonic)

// ---------------------------------------------------------------------------
// Kernel 1: x_gates = inputs @ W_ih^T + bias_ih  (unchanged)
// ---------------------------------------------------------------------------
__global__ __launch_bounds__(256) void xgemm_kernel(
    const float* __restrict__ A,
    const float* __restrict__ W,
    const float* __restrict__ bias,
    float* __restrict__ xg)
{
    __shared__ float As[16][132];
    __shared__ float Bs[16][132];

    const int m0 = blockIdx.y * 128;
    const int n0 = blockIdx.x * 128;
    const int t  = threadIdx.x;
    const int tr = t >> 4;
    const int tc = t & 15;
    const int lrow = t >> 2;
    const int lk4  = (t & 3) * 4;

    float acc[8][8] = {};

    for (int k0 = 0; k0 < Isz; k0 += 16) {
        #pragma unroll
        for (int p = 0; p < 2; p++) {
            int mm = lrow + p * 64;
            float4 va = *(const float4*)(A + (size_t)(m0 + mm) * Isz + k0 + lk4);
            As[lk4 + 0][mm] = va.x; As[lk4 + 1][mm] = va.y;
            As[lk4 + 2][mm] = va.z; As[lk4 + 3][mm] = va.w;
            float4 vw = *(const float4*)(W + (size_t)(n0 + mm) * Isz + k0 + lk4);
            Bs[lk4 + 0][mm] = vw.x; Bs[lk4 + 1][mm] = vw.y;
            Bs[lk4 + 2][mm] = vw.z; Bs[lk4 + 3][mm] = vw.w;
        }
        __syncthreads();

        #pragma unroll
        for (int kk = 0; kk < 16; kk++) {
            float a[8], b[8];
            #pragma unroll
            for (int i = 0; i < 8; i++) a[i] = As[kk][tr * 8 + i];
            #pragma unroll
            for (int j = 0; j < 8; j++) b[j] = Bs[kk][tc * 8 + j];
            #pragma unroll
            for (int i = 0; i < 8; i++)
                #pragma unroll
                for (int j = 0; j < 8; j++)
                    acc[i][j] += a[i] * b[j];
        }
        __syncthreads();
    }

    float bv[8];
    #pragma unroll
    for (int j = 0; j < 8; j++) bv[j] = bias[n0 + tc * 8 + j];

    #pragma unroll
    for (int i = 0; i < 8; i++) {
        int m = m0 + tr * 8 + i;
        int s = m & (Sq - 1);
        int b = m >> 9;
        float* dst = xg + (size_t)s * (Bsz * G3) + (size_t)b * G3 + n0 + tc * 8;
        #pragma unroll
        for (int j = 0; j < 8; j++) dst[j] = acc[i][j] + bv[j];
    }
}

// ---------------------------------------------------------------------------
// h0 [b][j] -> hT [j][b]   /   hT [j][b] -> dst [b][j]
// ---------------------------------------------------------------------------
__global__ void h0_transpose_kernel(const float* __restrict__ h0,
                                    float* __restrict__ hT)
{
    int idx = blockIdx.x * blockDim.x + threadIdx.x;
    int j = idx >> 6, b = idx & 63;
    hT[idx] = h0[(size_t)b * Hsz + j];
}

__global__ void hT_untranspose_kernel(const float* __restrict__ hT,
                                      float* __restrict__ dst)
{
    int idx = blockIdx.x * blockDim.x + threadIdx.x;
    int b = idx >> 10, j = idx & 1023;
    dst[idx] = hT[(size_t)j * Bsz + b];
}

// ---------------------------------------------------------------------------
// Packed fp32x2 helpers (Blackwell FFMA2 path — PTX-only, ptxas won't emit it)
// ---------------------------------------------------------------------------
__device__ __forceinline__ unsigned long long fma2(unsigned long long a,
                                                   unsigned long long b,
                                                   unsigned long long c) {
    unsigned long long d;
    asm("fma.rn.f32x2 %0, %1, %2, %3;" : "=l"(d) : "l"(a), "l"(b), "l"(c));
    return d;
}
__device__ __forceinline__ unsigned long long add2(unsigned long long a,
                                                   unsigned long long b) {
    unsigned long long d;
    asm("add.rn.f32x2 %0, %1, %2;" : "=l"(d) : "l"(a), "l"(b));
    return d;
}
__device__ __forceinline__ unsigned long long pack2(float v) {
    unsigned long long d;
    asm("mov.b64 %0, {%1, %1};" : "=l"(d) : "f"(v));
    return d;
}
__device__ __forceinline__ void unpack2(unsigned long long v, float& lo, float& hi) {
    asm("mov.b64 {%0, %1}, %2;" : "=f"(lo), "=f"(hi) : "l"(v));
}
__device__ __forceinline__ void cpa16(float* sp, const float* gp) {
    uint32_t sa = (uint32_t)__cvta_generic_to_shared(sp);
    asm volatile("cp.async.cg.shared.global [%0], [%1], 16;\n" :: "r"(sa), "l"(gp));
}

// ---------------------------------------------------------------------------
// Kernel 2: PERSISTENT GRU scan. One launch for all 512 steps.
//
// 128 blocks (j-tile of 8), 512 threads = 8 k-chunks x 64 threads, 1 CTA/SM.
// Whh slice (24 rows x 1024) resident in smem for the whole kernel.
// Per step: h [k][b] streamed via cp.async.cg double-buffered 16-k windows;
// thread tile 8 batches x 1 j x 3 gates as 12 packed f32x2 accumulators
// (h pairs come pre-packed from the transposed layout; W broadcast packed
// once per 4 FFMA2). Packed tree reduction over 8 chunks, fused epilogue,
// atomic grid barrier between steps.
// ---------------------------------------------------------------------------
#define NCH   8
#define KCH   (Hsz / NCH)            // 128
#define HW    16                     // window k-size
#define NWIN  (KCH / HW)             // 8
#define WSTR  1028                   // padded W row stride (floats)
#define WS_F  (24 * WSTR)            // 24672 floats (98,688 B)
#define HBUF_F (HW * 64)             // 1024 floats per chunk per buffer
#define SMEM_F (WS_F + NCH * 2 * HBUF_F)   // 41,056 floats
#define SMEM_BYTES (SMEM_F * 4)            // 164,224 B

extern __shared__ float smem[];

__global__ __launch_bounds__(512, 1) void gru_scan_kernel(
    const float* __restrict__ xg,     // [S][B][G3]
    const float* __restrict__ Whh,    // [G3][H]
    const float* __restrict__ bhh,    // [G3]
    float* __restrict__ hT,           // g_hT base: 2 x [H][B]
    float* __restrict__ out)          // [B][S][H]
{
    const int t  = threadIdx.x;
    const int c  = t >> 6;            // k-chunk 0..7 (warp-uniform)
    const int lt = t & 63;
    const int j0 = blockIdx.x * 8;
    const int kc = c * KCH;
    const int jj = lt >> 3;           // 0..7
    const int b0 = (lt & 7) * 8;      // 0,8,...,56
    const int j  = j0 + jj;

    // ---- load W slice into smem once ----
    #pragma unroll
    for (int i = 0; i < 12; i++) {
        int f = t + 512 * i;          // 0..6143 float4 slots
        int r = f >> 8;               // 0..23 (gate*8 + jr)
        int kq = (f & 255) * 4;
        int gate = r >> 3, jr = r & 7;
        *(float4*)&smem[r * WSTR + kq] =
            *(const float4*)(Whh + (size_t)(gate * Hsz + j0 + jr) * Hsz + kq);
    }

    unsigned base = 0;
    if (t == 0) base = *(volatile unsigned*)&g_bar_phase;

    float bhr = 0.f, bhz = 0.f, bhn = 0.f;
    if (c == 0) {
        bhr = bhh[j];
        bhz = bhh[Hsz + j];
        bhn = bhh[2 * Hsz + j];
    }
    __syncthreads();   // W resident

    const float* wr_row = smem + jj * WSTR;
    const float* wz_row = smem + (8 + jj) * WSTR;
    const float* wn_row = smem + (16 + jj) * WSTR;

    for (int s = 0; s < Sq; s++) {
        const float* hin  = hT + (size_t)(s & 1) * (Hsz * Bsz);
        float*       hout = hT + (size_t)((s + 1) & 1) * (Hsz * Bsz);
        const float* xs   = xg + (size_t)s * (Bsz * G3);

        // ---- prefetch epilogue operands (c==0 warps only) ----
        float xr_p[8], xz_p[8], xn_p[8], hp_p[8];
        if (c == 0) {
            #pragma unroll
            for (int i = 0; i < 8; i++) {
                const float* xb = xs + (size_t)(b0 + i) * G3 + j;
                xr_p[i] = __ldg(xb);
                xz_p[i] = __ldg(xb + Hsz);
                xn_p[i] = __ldg(xb + 2 * Hsz);
            }
            // h read L2-only (L1 not flushed inside persistent kernel)
            float4 h4a = __ldcg((const float4*)(hin + (size_t)j * 64 + b0));
            float4 h4b = __ldcg((const float4*)(hin + (size_t)j * 64 + b0 + 4));
            hp_p[0] = h4a.x; hp_p[1] = h4a.y; hp_p[2] = h4a.z; hp_p[3] = h4a.w;
            hp_p[4] = h4b.x; hp_p[5] = h4b.y; hp_p[6] = h4b.z; hp_p[7] = h4b.w;
        }

        unsigned long long accr[4] = {}, accz[4] = {}, accn[4] = {};

        // ---- stream h through double-buffered windows ----
        {
            float* hs0 = smem + WS_F + (c * 2 + 0) * HBUF_F;
            const float* hp = hin + (size_t)kc * 64;
            #pragma unroll
            for (int i = 0; i < 4; i++) {
                int f = (lt + 64 * i) * 4;
                cpa16(hs0 + f, hp + f);
            }
            asm volatile("cp.async.commit_group;\n" ::: "memory");
        }

        for (int w = 0; w < NWIN; w++) {
            if (w + 1 < NWIN) {
                float* hsn = smem + WS_F + (c * 2 + ((w + 1) & 1)) * HBUF_F;
                const float* hp = hin + (size_t)(kc + (w + 1) * HW) * 64;
                #pragma unroll
                for (int i = 0; i < 4; i++) {
                    int f = (lt + 64 * i) * 4;
                    cpa16(hsn + f, hp + f);
                }
                asm volatile("cp.async.commit_group;\n" ::: "memory");
                asm volatile("cp.async.wait_group 1;\n" ::: "memory");
            } else {
                asm volatile("cp.async.wait_group 0;\n" ::: "memory");
            }
            __syncthreads();

            const float* hs = smem + WS_F + (c * 2 + (w & 1)) * HBUF_F;
            const int kcol = kc + w * HW;

            #pragma unroll
            for (int kk = 0; kk < HW; kk += 4) {
                float4 a = *(const float4*)(wr_row + kcol + kk);
                float4 bz = *(const float4*)(wz_row + kcol + kk);
                float4 d = *(const float4*)(wn_row + kcol + kk);
                unsigned long long wrp[4] = {pack2(a.x),  pack2(a.y),  pack2(a.z),  pack2(a.w)};
                unsigned long long wzp[4] = {pack2(bz.x), pack2(bz.y), pack2(bz.z), pack2(bz.w)};
                unsigned long long wnp[4] = {pack2(d.x),  pack2(d.y),  pack2(d.z),  pack2(d.w)};
                #pragma unroll
                for (int u = 0; u < 4; u++) {
                    ulonglong2 h01 = *(const ulonglong2*)(hs + (kk + u) * 64 + b0);
                    ulonglong2 h23 = *(const ulonglong2*)(hs + (kk + u) * 64 + b0 + 4);
                    accr[0] = fma2(h01.x, wrp[u], accr[0]);
                    accr[1] = fma2(h01.y, wrp[u], accr[1]);
                    accr[2] = fma2(h23.x, wrp[u], accr[2]);
                    accr[3] = fma2(h23.y, wrp[u], accr[3]);
                    accz[0] = fma2(h01.x, wzp[u], accz[0]);
                    accz[1] = fma2(h01.y, wzp[u], accz[1]);
                    accz[2] = fma2(h23.x, wzp[u], accz[2]);
                    accz[3] = fma2(h23.y, wzp[u], accz[3]);
                    accn[0] = fma2(h01.x, wnp[u], accn[0]);
                    accn[1] = fma2(h01.y, wnp[u], accn[1]);
                    accn[2] = fma2(h23.x, wnp[u], accn[2]);
                    accn[3] = fma2(h23.y, wnp[u], accn[3]);
                }
            }
            __syncthreads();
        }

        // ---- packed tree reduction over 8 chunks (reuse h buffer area) ----
        unsigned long long* red = (unsigned long long*)(smem + WS_F);
        if (c >= 4) {
            unsigned long long* dp = red + (size_t)((c - 4) * 64 + lt) * 12;
            #pragma unroll
            for (int p = 0; p < 4; p++) { dp[p] = accr[p]; dp[4 + p] = accz[p]; dp[8 + p] = accn[p]; }
        }
        __syncthreads();
        if (c < 4) {
            const unsigned long long* sp = red + (size_t)(c * 64 + lt) * 12;
            #pragma unroll
            for (int p = 0; p < 4; p++) {
                accr[p] = add2(accr[p], sp[p]);
                accz[p] = add2(accz[p], sp[4 + p]);
                accn[p] = add2(accn[p], sp[8 + p]);
            }
        }
        __syncthreads();
        if (c == 2 || c == 3) {
            unsigned long long* dp = red + (size_t)((c - 2) * 64 + lt) * 12;
            #pragma unroll
            for (int p = 0; p < 4; p++) { dp[p] = accr[p]; dp[4 + p] = accz[p]; dp[8 + p] = accn[p]; }
        }
        __syncthreads();
        if (c < 2) {
            const unsigned long long* sp = red + (size_t)(c * 64 + lt) * 12;
            #pragma unroll
            for (int p = 0; p < 4; p++) {
                accr[p] = add2(accr[p], sp[p]);
                accz[p] = add2(accz[p], sp[4 + p]);
                accn[p] = add2(accn[p], sp[8 + p]);
            }
        }
        __syncthreads();
        if (c == 1) {
            unsigned long long* dp = red + (size_t)lt * 12;
            #pragma unroll
            for (int p = 0; p < 4; p++) { dp[p] = accr[p]; dp[4 + p] = accz[p]; dp[8 + p] = accn[p]; }
        }
        __syncthreads();

        // ---- fused pointwise epilogue (c==0) ----
        if (c == 0) {
            const unsigned long long* sp = red + (size_t)lt * 12;
            float ar[8], az[8], an[8];
            #pragma unroll
            for (int p = 0; p < 4; p++) {
                unpack2(add2(accr[p], sp[p]),     ar[2 * p], ar[2 * p + 1]);
                unpack2(add2(accz[p], sp[4 + p]), az[2 * p], az[2 * p + 1]);
                unpack2(add2(accn[p], sp[8 + p]), an[2 * p], an[2 * p + 1]);
            }
            float hnv[8];
            #pragma unroll
            for (int i = 0; i < 8; i++) {
                float r = 1.f / (1.f + expf(-(xr_p[i] + ar[i] + bhr)));
                float z = 1.f / (1.f + expf(-(xz_p[i] + az[i] + bhz)));
                float n = tanhf(xn_p[i] + r * (an[i] + bhn));
                hnv[i] = (1.f - z) * n + z * hp_p[i];
                out[(size_t)(b0 + i) * Sq * Hsz + (size_t)s * Hsz + j] = hnv[i];
            }
            *(float4*)&hout[(size_t)j * 64 + b0]     = make_float4(hnv[0], hnv[1], hnv[2], hnv[3]);
            *(float4*)&hout[(size_t)j * 64 + b0 + 4] = make_float4(hnv[4], hnv[5], hnv[6], hnv[7]);
        }

        // ---- grid barrier between steps ----
        __syncthreads();
        if (t == 0 && s + 1 < Sq) {
            __threadfence();                         // release h writes
            unsigned arr = atomicAdd(&g_bar_count, 1);
            if (arr == gridDim.x - 1) {
                atomicExch(&g_bar_count, 0);
                __threadfence();
                atomicAdd(&g_bar_phase, 1);
            } else {
                unsigned target = (unsigned)(s + 1);
                unsigned spins = 0;
                while ((unsigned)(*(volatile unsigned*)&g_bar_phase - base) < target) {
                    if (++spins > 100000000u) break;   // safety: fail loud, not hung
                }
                __threadfence();                      // acquire
            }
        }
        __syncthreads();
    }
}

// ---------------------------------------------------------------------------
// kernel_launch (graph-capturable: kernel launches only)
// ---------------------------------------------------------------------------
extern "C" void kernel_launch(void* const* d_in, const int* in_sizes, int n_in,
                              void* d_out, int out_size)
{
    const float* inputs = (const float*)d_in[0];
    const float* h0     = (const float*)d_in[1];
    const float* Wih    = (const float*)d_in[2];
    const float* Whh    = (const float*)d_in[3];
    const float* bih    = (const float*)d_in[4];
    const float* bhh    = (const float*)d_in[5];
    float* out = (float*)d_out;

    float* xg = nullptr;
    float* hT = nullptr;
    cudaGetSymbolAddress((void**)&xg, g_xg);
    cudaGetSymbolAddress((void**)&hT, g_hT);

    cudaFuncSetAttribute(gru_scan_kernel,
                         cudaFuncAttributeMaxDynamicSharedMemorySize, SMEM_BYTES);

    // Phase A: input projections + h0 transpose
    dim3 ggrid(G3 / 128, (Bsz * Sq) / 128);   // (24, 256)
    xgemm_kernel<<<ggrid, 256>>>(inputs, Wih, bih, xg);
    h0_transpose_kernel<<<(Hsz * Bsz) / 256, 256>>>(h0, hT);

    // Phase B: whole scan in ONE persistent kernel (128 blocks, all resident)
    gru_scan_kernel<<<128, 512, SMEM_BYTES>>>(xg, Whh, bhh, hT, out);

    // hn: final h in buffer 0, transposed -> untranspose into tail of out
    hT_untranspose_kernel<<<(Hsz * Bsz) / 256, 256>>>(
        hT, out + (size_t)Bsz * Sq * Hsz);
}

// round 9
// speedup vs baseline: 2.8428x; 1.6170x over previous
#include <cuda_runtime.h>
#include <cuda_bf16.h>
#include <cstddef>
#include <cstdint>

#define Bsz 64
#define Sq  512
#define Isz 512
#define Hsz 1024
#define G3  3072   // 3*Hsz

// Scratch (static device allocations; no cudaMalloc anywhere)
__device__ float g_xg[(size_t)Sq * Bsz * G3];              // x_gates [s][b][g]
__device__ __nv_bfloat16 g_hb[2][2][Bsz * Hsz];            // h ping-pong, [ping][hi/lo][b][j]
__device__ unsigned g_bar_count;                           // grid barrier arrivals
__device__ unsigned g_bar_phase;                           // grid barrier phase (monotonic)

// ---------------------------------------------------------------------------
// Kernel 1: x_gates = inputs @ W_ih^T + bias_ih  (unchanged, near fp32 roofline)
// ---------------------------------------------------------------------------
__global__ __launch_bounds__(256) void xgemm_kernel(
    const float* __restrict__ A,
    const float* __restrict__ W,
    const float* __restrict__ bias,
    float* __restrict__ xg)
{
    __shared__ float As[16][132];
    __shared__ float Bs[16][132];

    const int m0 = blockIdx.y * 128;
    const int n0 = blockIdx.x * 128;
    const int t  = threadIdx.x;
    const int tr = t >> 4;
    const int tc = t & 15;
    const int lrow = t >> 2;
    const int lk4  = (t & 3) * 4;

    float acc[8][8] = {};

    for (int k0 = 0; k0 < Isz; k0 += 16) {
        #pragma unroll
        for (int p = 0; p < 2; p++) {
            int mm = lrow + p * 64;
            float4 va = *(const float4*)(A + (size_t)(m0 + mm) * Isz + k0 + lk4);
            As[lk4 + 0][mm] = va.x; As[lk4 + 1][mm] = va.y;
            As[lk4 + 2][mm] = va.z; As[lk4 + 3][mm] = va.w;
            float4 vw = *(const float4*)(W + (size_t)(n0 + mm) * Isz + k0 + lk4);
            Bs[lk4 + 0][mm] = vw.x; Bs[lk4 + 1][mm] = vw.y;
            Bs[lk4 + 2][mm] = vw.z; Bs[lk4 + 3][mm] = vw.w;
        }
        __syncthreads();

        #pragma unroll
        for (int kk = 0; kk < 16; kk++) {
            float a[8], b[8];
            #pragma unroll
            for (int i = 0; i < 8; i++) a[i] = As[kk][tr * 8 + i];
            #pragma unroll
            for (int j = 0; j < 8; j++) b[j] = Bs[kk][tc * 8 + j];
            #pragma unroll
            for (int i = 0; i < 8; i++)
                #pragma unroll
                for (int j = 0; j < 8; j++)
                    acc[i][j] += a[i] * b[j];
        }
        __syncthreads();
    }

    float bv[8];
    #pragma unroll
    for (int j = 0; j < 8; j++) bv[j] = bias[n0 + tc * 8 + j];

    #pragma unroll
    for (int i = 0; i < 8; i++) {
        int m = m0 + tr * 8 + i;
        int s = m & (Sq - 1);
        int b = m >> 9;
        float* dst = xg + (size_t)s * (Bsz * G3) + (size_t)b * G3 + n0 + tc * 8;
        #pragma unroll
        for (int j = 0; j < 8; j++) dst[j] = acc[i][j] + bv[j];
    }
}

// ---------------------------------------------------------------------------
// Prep: h0 fp32 [b][j] -> bf16 hi/lo into ping buffer 0
// ---------------------------------------------------------------------------
__global__ void h0_prep_kernel(const float* __restrict__ h0,
                               __nv_bfloat16* __restrict__ hhi,
                               __nv_bfloat16* __restrict__ hlo)
{
    int idx = blockIdx.x * blockDim.x + threadIdx.x;   // 65536
    float v = h0[idx];
    __nv_bfloat16 hi = __float2bfloat16(v);
    hhi[idx] = hi;
    hlo[idx] = __float2bfloat16(v - __bfloat162float(hi));
}

// hn = outputs[:, S-1, :]  (exact fp32 copy from out itself)
__global__ void hn_copy_kernel(float* __restrict__ out)
{
    int idx = blockIdx.x * blockDim.x + threadIdx.x;   // 65536
    int b = idx >> 10, j = idx & 1023;
    out[(size_t)Bsz * Sq * Hsz + idx] =
        out[(size_t)b * Sq * Hsz + (size_t)(Sq - 1) * Hsz + j];
}

// ---------------------------------------------------------------------------
// helpers
// ---------------------------------------------------------------------------
__device__ __forceinline__ uint32_t smem_u32(const void* p) {
    uint32_t a;
    asm("{ .reg .u64 t; cvta.to.shared.u64 t, %1; cvt.u32.u64 %0, t; }"
        : "=r"(a) : "l"(p));
    return a;
}
__device__ __forceinline__ void cpa16(uint32_t sdst, const void* gp) {
    asm volatile("cp.async.cg.shared.global [%0], [%1], 16;\n"
                 :: "r"(sdst), "l"(gp) : "memory");
}
__device__ __forceinline__ void ldm4(uint32_t& r0, uint32_t& r1,
                                     uint32_t& r2, uint32_t& r3, uint32_t addr) {
    asm volatile("ldmatrix.sync.aligned.m8n8.x4.shared.b16 {%0,%1,%2,%3}, [%4];"
                 : "=r"(r0), "=r"(r1), "=r"(r2), "=r"(r3) : "r"(addr));
}
__device__ __forceinline__ void mma_bf16(float& d0, float& d1, float& d2, float& d3,
                                         uint32_t a0, uint32_t a1, uint32_t a2, uint32_t a3,
                                         uint32_t b0, uint32_t b1) {
    asm volatile(
        "mma.sync.aligned.m16n8k16.row.col.f32.bf16.bf16.f32 "
        "{%0,%1,%2,%3}, {%4,%5,%6,%7}, {%8,%9}, {%0,%1,%2,%3};"
        : "+f"(d0), "+f"(d1), "+f"(d2), "+f"(d3)
        : "r"(a0), "r"(a1), "r"(a2), "r"(a3), "r"(b0), "r"(b1));
}

// ---------------------------------------------------------------------------
// Kernel 2: PERSISTENT bf16-split mma.sync GRU scan (base ISA, no 'a' features)
//
// 128 blocks x 512 threads, 1 CTA/SM (smem-limited), all co-resident.
// Block owns N=24 cols (8 j x 3 gates). W -> bf16 hi/lo in smem once.
// Per step: h (bf16 hi/lo, [b][k]) staged via cp.async double-buffered
// k-windows of 128; 12 compute warps = 4 mtiles x 3 ntiles, each does
// 8 ldmatrix + B LDS + 3 HMMA per ktile, full-K fragment accumulation.
// Epilogue: frags -> smem D -> fused gates; h' stored as bf16 hi/lo.
// ---------------------------------------------------------------------------
#define OFF_D   0u                    // 64 x 26 fp32 = 6656 B
#define OFF_W   8192u                 // W hi then lo
#define WROWB   2064u                 // 1024 bf16 = 2048 B + 16 pad (bank-shift 4)
#define OFF_WLO (OFF_W + 24u * WROWB)         // 57728
#define OFF_H   107520u               // h window buffers
#define HROWB   272u                  // 128 bf16 = 256 B + 16 pad
#define HHALF   (64u * HROWB)         // 17408 (one half: hi or lo)
#define HBUF    (2u * HHALF)          // 34816 (hi+lo)
#define SCAN_SMEM (OFF_H + 2u * HBUF)         // 177152 B

extern __shared__ char smem_raw[];

__global__ __launch_bounds__(512, 1) void gru_scan_kernel(
    const float* __restrict__ xg,              // [S][B][G3]
    const float* __restrict__ Whh,             // [G3][H] fp32
    const float* __restrict__ bhh,             // [G3]
    __nv_bfloat16* __restrict__ hb,            // g_hb base: [2][2][B*H]
    float* __restrict__ out)                   // [B][S][H]
{
    const uint32_t sb = smem_u32(smem_raw);
    const int t    = threadIdx.x;
    const int wid  = t >> 5;
    const int lane = t & 31;
    const int j0   = blockIdx.x * 8;

    // ---- W -> smem as bf16 hi/lo (once) ----
    #pragma unroll
    for (int i = 0; i < 48; i++) {
        int idx = t + 512 * i;            // 0..24575
        int r = idx >> 10;                // 0..23 = gate*8 + jr
        int k = idx & 1023;
        int gate = r >> 3, jr = r & 7;
        float v = Whh[(size_t)(gate * Hsz + j0 + jr) * Hsz + k];
        __nv_bfloat16 hi = __float2bfloat16(v);
        __nv_bfloat16 lo = __float2bfloat16(v - __bfloat162float(hi));
        *(__nv_bfloat16*)(smem_raw + OFF_W   + r * WROWB + k * 2) = hi;
        *(__nv_bfloat16*)(smem_raw + OFF_WLO + r * WROWB + k * 2) = lo;
    }
    __syncthreads();

    unsigned base = 0;
    if (t == 0) base = *(volatile unsigned*)&g_bar_phase;

    // ---- compute-warp constants ----
    const int nt = wid >> 2;              // 0..2 (gate tile)
    const int mt = wid & 3;               // 0..3 (batch tile)
    // A (ldmatrix) lane address offset within an h half-buffer
    const int sub   = lane >> 3;
    const int a_row = mt * 16 + (lane & 7) + ((sub & 1) << 3);
    const uint32_t a_off = (uint32_t)(a_row * HROWB + ((sub >> 1) << 4));
    // B lane offsets (W rows nt*8 + g)
    const int bg   = lane >> 2;
    const int btid = lane & 3;
    const uint32_t* whi_p = (const uint32_t*)(smem_raw + OFF_W   + (nt * 8 + bg) * WROWB);
    const uint32_t* wlo_p = (const uint32_t*)(smem_raw + OFF_WLO + (nt * 8 + bg) * WROWB);

    // epilogue biases (t<64: thread t == batch t)
    float bhr[8], bhz[8], bhn[8];
    if (t < 64) {
        #pragma unroll
        for (int jj = 0; jj < 8; jj++) {
            bhr[jj] = bhh[j0 + jj];
            bhz[jj] = bhh[Hsz + j0 + jj];
            bhn[jj] = bhh[2 * Hsz + j0 + jj];
        }
    }

    float* Dp = (float*)(smem_raw + OFF_D);

    for (int s = 0; s < Sq; s++) {
        const int pin  = s & 1, pout = (s + 1) & 1;
        const __nv_bfloat16* hin_hi = hb + (size_t)pin * 2 * (Bsz * Hsz);
        const __nv_bfloat16* hin_lo = hin_hi + (Bsz * Hsz);
        __nv_bfloat16* hout_hi = hb + (size_t)pout * 2 * (Bsz * Hsz);
        __nv_bfloat16* hout_lo = hout_hi + (Bsz * Hsz);
        const float* xgs = xg + (size_t)s * (Bsz * G3);

        // ---- epilogue operand prefetch (warps 0-1) ----
        float xr[8], xz[8], xn[8], hp[8];
        if (t < 64) {
            const float* xb = xgs + (size_t)t * G3 + j0;
            float4 v0 = __ldg((const float4*)xb);
            float4 v1 = __ldg((const float4*)(xb + 4));
            xr[0]=v0.x; xr[1]=v0.y; xr[2]=v0.z; xr[3]=v0.w;
            xr[4]=v1.x; xr[5]=v1.y; xr[6]=v1.z; xr[7]=v1.w;
            v0 = __ldg((const float4*)(xb + Hsz));
            v1 = __ldg((const float4*)(xb + Hsz + 4));
            xz[0]=v0.x; xz[1]=v0.y; xz[2]=v0.z; xz[3]=v0.w;
            xz[4]=v1.x; xz[5]=v1.y; xz[6]=v1.z; xz[7]=v1.w;
            v0 = __ldg((const float4*)(xb + 2 * Hsz));
            v1 = __ldg((const float4*)(xb + 2 * Hsz + 4));
            xn[0]=v0.x; xn[1]=v0.y; xn[2]=v0.z; xn[3]=v0.w;
            xn[4]=v1.x; xn[5]=v1.y; xn[6]=v1.z; xn[7]=v1.w;
            // reconstruct h_prev from bf16 hi+lo (L2-only reads)
            uint4 uh = __ldcg((const uint4*)(hin_hi + (size_t)t * Hsz + j0));
            uint4 ul = __ldcg((const uint4*)(hin_lo + (size_t)t * Hsz + j0));
            const __nv_bfloat16* ph = (const __nv_bfloat16*)&uh;
            const __nv_bfloat16* pl = (const __nv_bfloat16*)&ul;
            #pragma unroll
            for (int jj = 0; jj < 8; jj++)
                hp[jj] = __bfloat162float(ph[jj]) + __bfloat162float(pl[jj]);
        }

        float d0 = 0.f, d1 = 0.f, d2 = 0.f, d3 = 0.f;

        // staging: window w (k in [128w,128w+128)), 4 cpa16 per thread
        auto stage = [&](int w) {
            int buf = w & 1;
            #pragma unroll
            for (int i = 0; i < 4; i++) {
                int c    = t + 512 * i;          // 0..2047
                int half = c >> 10;
                int rem  = c & 1023;
                int row  = rem >> 4;
                int cq   = rem & 15;
                const char* src = (const char*)(half ? hin_lo : hin_hi)
                                  + row * 2048 + w * 256 + cq * 16;
                cpa16(sb + OFF_H + buf * HBUF + half * HHALF
                         + row * HROWB + cq * 16, src);
            }
            asm volatile("cp.async.commit_group;\n" ::: "memory");
        };

        stage(0);

        #pragma unroll 1
        for (int w = 0; w < 8; w++) {
            if (w < 7) {
                stage(w + 1);
                asm volatile("cp.async.wait_group 1;\n" ::: "memory");
            } else {
                asm volatile("cp.async.wait_group 0;\n" ::: "memory");
            }
            __syncthreads();

            if (wid < 12) {
                const uint32_t abase = sb + OFF_H + (uint32_t)(w & 1) * HBUF + a_off;
                #pragma unroll
                for (int kt = 0; kt < 8; kt++) {
                    uint32_t ah0, ah1, ah2, ah3, al0, al1, al2, al3;
                    ldm4(ah0, ah1, ah2, ah3, abase + kt * 32);
                    ldm4(al0, al1, al2, al3, abase + HHALF + kt * 32);
                    int kw = (w * 8 + kt) * 8 + btid;   // u32 index into W row
                    uint32_t bh0 = whi_p[kw], bh1 = whi_p[kw + 4];
                    uint32_t bl0 = wlo_p[kw], bl1 = wlo_p[kw + 4];
                    mma_bf16(d0, d1, d2, d3, ah0, ah1, ah2, ah3, bh0, bh1);
                    mma_bf16(d0, d1, d2, d3, ah0, ah1, ah2, ah3, bl0, bl1);
                    mma_bf16(d0, d1, d2, d3, al0, al1, al2, al3, bh0, bh1);
                }
            }
            __syncthreads();
        }

        // ---- fragments -> smem D[64][24] ----
        if (wid < 12) {
            int m  = mt * 16 + (lane >> 2);
            int nc = nt * 8 + 2 * (lane & 3);
            Dp[m * 26 + nc]           = d0;
            Dp[m * 26 + nc + 1]       = d1;
            Dp[(m + 8) * 26 + nc]     = d2;
            Dp[(m + 8) * 26 + nc + 1] = d3;
        }
        __syncthreads();

        // ---- fused pointwise epilogue (threads 0-63 = batches) ----
        if (t < 64) {
            __nv_bfloat16 whi[8], wlo[8];
            float hnv[8];
            #pragma unroll
            for (int jj = 0; jj < 8; jj++) {
                float ar = Dp[t * 26 + jj];
                float az = Dp[t * 26 + 8 + jj];
                float an = Dp[t * 26 + 16 + jj];
                float r = 1.f / (1.f + expf(-(xr[jj] + ar + bhr[jj])));
                float z = 1.f / (1.f + expf(-(xz[jj] + az + bhz[jj])));
                float n = tanhf(xn[jj] + r * (an + bhn[jj]));
                float h = (1.f - z) * n + z * hp[jj];
                hnv[jj] = h;
                __nv_bfloat16 hi = __float2bfloat16(h);
                whi[jj] = hi;
                wlo[jj] = __float2bfloat16(h - __bfloat162float(hi));
            }
            float* op = out + (size_t)t * Sq * Hsz + (size_t)s * Hsz + j0;
            *(float4*)op       = make_float4(hnv[0], hnv[1], hnv[2], hnv[3]);
            *(float4*)(op + 4) = make_float4(hnv[4], hnv[5], hnv[6], hnv[7]);
            *(uint4*)(hout_hi + (size_t)t * Hsz + j0) = *(uint4*)whi;
            *(uint4*)(hout_lo + (size_t)t * Hsz + j0) = *(uint4*)wlo;
        }

        // ---- grid barrier between steps ----
        __syncthreads();
        if (t == 0 && s + 1 < Sq) {
            __threadfence();                         // release h writes
            unsigned arr = atomicAdd(&g_bar_count, 1);
            if (arr == gridDim.x - 1) {
                atomicExch(&g_bar_count, 0);
                __threadfence();
                atomicAdd(&g_bar_phase, 1);
            } else {
                unsigned target = (unsigned)(s + 1);
                unsigned spins = 0;
                while ((unsigned)(*(volatile unsigned*)&g_bar_phase - base) < target) {
                    if (++spins > 200000000u) break;   // fail loud, not hung
                }
                __threadfence();                     // acquire
            }
        }
        __syncthreads();
    }
}

// ---------------------------------------------------------------------------
// kernel_launch (graph-capturable: kernel launches only)
// ---------------------------------------------------------------------------
extern "C" void kernel_launch(void* const* d_in, const int* in_sizes, int n_in,
                              void* d_out, int out_size)
{
    const float* inputs = (const float*)d_in[0];
    const float* h0     = (const float*)d_in[1];
    const float* Wih    = (const float*)d_in[2];
    const float* Whh    = (const float*)d_in[3];
    const float* bih    = (const float*)d_in[4];
    const float* bhh    = (const float*)d_in[5];
    float* out = (float*)d_out;

    float* xg = nullptr;
    __nv_bfloat16* hb = nullptr;
    cudaGetSymbolAddress((void**)&xg, g_xg);
    cudaGetSymbolAddress((void**)&hb, g_hb);

    cudaFuncSetAttribute(gru_scan_kernel,
                         cudaFuncAttributeMaxDynamicSharedMemorySize, SCAN_SMEM);

    // Phase A: input projections (one GEMM) + h0 -> bf16 hi/lo (ping 0)
    dim3 ggrid(G3 / 128, (Bsz * Sq) / 128);   // (24, 256)
    xgemm_kernel<<<ggrid, 256>>>(inputs, Wih, bih, xg);
    h0_prep_kernel<<<(Bsz * Hsz) / 256, 256>>>(h0, hb, hb + Bsz * Hsz);

    // Phase B: whole scan in ONE persistent mma.sync kernel
    gru_scan_kernel<<<128, 512, SCAN_SMEM>>>(xg, Whh, bhh, hb, out);

    // hn = outputs[:, S-1, :] (exact fp32)
    hn_copy_kernel<<<(Bsz * Hsz) / 256, 256>>>(out);
}

// round 10
// speedup vs baseline: 3.3258x; 1.1699x over previous
#include <cuda_runtime.h>
#include <cuda_bf16.h>
#include <cstddef>
#include <cstdint>

#define Bsz 64
#define Sq  512
#define Isz 512
#define Hsz 1024
#define G3  3072   // 3*Hsz

// Scratch (static device allocations; no cudaMalloc anywhere)
__device__ float g_xg[(size_t)Sq * Bsz * G3];              // x_gates [s][b][g]
__device__ __nv_bfloat16 g_hb[2][2][Bsz * Hsz];            // h ping-pong [ping][hi/lo][b][j]
__device__ __nv_bfloat16 g_Ahi[(size_t)Bsz * Sq * Isz];    // inputs hi  [m][k]
__device__ __nv_bfloat16 g_Alo[(size_t)Bsz * Sq * Isz];    // inputs lo
__device__ __nv_bfloat16 g_Whi[(size_t)G3 * Isz];          // Wih hi [n][k]
__device__ __nv_bfloat16 g_Wlo[(size_t)G3 * Isz];          // Wih lo
__device__ unsigned g_bar_count;
__device__ unsigned g_bar_phase;

// ---------------------------------------------------------------------------
// helpers
// ---------------------------------------------------------------------------
__device__ __forceinline__ uint32_t smem_u32(const void* p) {
    uint32_t a;
    asm("{ .reg .u64 t; cvta.to.shared.u64 t, %1; cvt.u32.u64 %0, t; }"
        : "=r"(a) : "l"(p));
    return a;
}
__device__ __forceinline__ void cpa16(uint32_t sdst, const void* gp) {
    asm volatile("cp.async.cg.shared.global [%0], [%1], 16;\n"
                 :: "r"(sdst), "l"(gp) : "memory");
}
__device__ __forceinline__ void ldm4(uint32_t& r0, uint32_t& r1,
                                     uint32_t& r2, uint32_t& r3, uint32_t addr) {
    asm volatile("ldmatrix.sync.aligned.m8n8.x4.shared.b16 {%0,%1,%2,%3}, [%4];"
                 : "=r"(r0), "=r"(r1), "=r"(r2), "=r"(r3) : "r"(addr));
}
__device__ __forceinline__ void mma_bf16(float& d0, float& d1, float& d2, float& d3,
                                         uint32_t a0, uint32_t a1, uint32_t a2, uint32_t a3,
                                         uint32_t b0, uint32_t b1) {
    asm volatile(
        "mma.sync.aligned.m16n8k16.row.col.f32.bf16.bf16.f32 "
        "{%0,%1,%2,%3}, {%4,%5,%6,%7}, {%8,%9}, {%0,%1,%2,%3};"
        : "+f"(d0), "+f"(d1), "+f"(d2), "+f"(d3)
        : "r"(a0), "r"(a1), "r"(a2), "r"(a3), "r"(b0), "r"(b1));
}

// ---------------------------------------------------------------------------
// fp32 -> bf16 hi/lo split (vectorized, once)
// ---------------------------------------------------------------------------
__global__ void split_kernel(const float* __restrict__ src,
                             __nv_bfloat16* __restrict__ hi,
                             __nv_bfloat16* __restrict__ lo)
{
    size_t i = (size_t)blockIdx.x * blockDim.x + threadIdx.x;   // float4 index
    float4 v = ((const float4*)src)[i];
    float f[4] = {v.x, v.y, v.z, v.w};
    __nv_bfloat16 h[4], l[4];
    #pragma unroll
    for (int q = 0; q < 4; q++) {
        h[q] = __float2bfloat16(f[q]);
        l[q] = __float2bfloat16(f[q] - __bfloat162float(h[q]));
    }
    ((uint2*)hi)[i] = *(uint2*)h;
    ((uint2*)lo)[i] = *(uint2*)l;
}

// h0 fp32 [b][j] -> bf16 hi/lo into ping buffer 0
__global__ void h0_prep_kernel(const float* __restrict__ h0,
                               __nv_bfloat16* __restrict__ hhi,
                               __nv_bfloat16* __restrict__ hlo)
{
    int idx = blockIdx.x * blockDim.x + threadIdx.x;
    float v = h0[idx];
    __nv_bfloat16 hi = __float2bfloat16(v);
    hhi[idx] = hi;
    hlo[idx] = __float2bfloat16(v - __bfloat162float(hi));
}

// ---------------------------------------------------------------------------
// Kernel 1: x_gates = inputs @ W_ih^T + bias_ih on tensor cores (bf16 split-2)
//
// Block 128m x 128n, 256 threads = 8 warps (2m x 4n), warp tile m64 x n32.
// K=512 streamed in 16 windows of 32, double-buffered cp.async.
// Per ktile per warp: 8 ldmatrix.x4 (A hi/lo, 4 m-blocks) + 16 LDS.32 (B frags)
// + 48 HMMA (4m x 4n x 3 chains). Epilogue adds bias, scatters to [s][b][g].
// ---------------------------------------------------------------------------
#define XROWB 80u                       // 32 bf16 = 64B + 16 pad (conflict-free)
#define XHALF (128u * XROWB)            // 10240 B per operand-half per window
#define XBUF  (4u * XHALF)              // Ahi,Alo,Bhi,Blo = 40960 B
#define XGEMM_SMEM (2u * XBUF)          // 81920 B

extern __shared__ char xsmem[];

__global__ __launch_bounds__(256) void xgemm_mma_kernel(
    const __nv_bfloat16* __restrict__ Ahi,
    const __nv_bfloat16* __restrict__ Alo,
    const __nv_bfloat16* __restrict__ Whi,
    const __nv_bfloat16* __restrict__ Wlo,
    const float* __restrict__ bias,
    float* __restrict__ xg)
{
    const uint32_t sb = smem_u32(xsmem);
    const int t    = threadIdx.x;
    const int wid  = t >> 5;
    const int lane = t & 31;
    const int m0   = blockIdx.y * 128;
    const int n0   = blockIdx.x * 128;
    const int wm   = (wid >> 2) * 64;
    const int wn   = (wid & 3) * 32;

    // ldmatrix lane geometry (within an m16 x k16 block)
    const int sub = lane >> 3;
    const uint32_t a_lane_off =
        (uint32_t)(((lane & 7) + ((sub & 1) << 3)) * XROWB + ((sub >> 1) << 4));

    // B frag geometry
    const int bg   = lane >> 2;        // n within 8
    const int btid = lane & 3;

    float acc[4][4][4] = {};

    // staging: 2048 cp16 per window, 8 per thread
    auto stage = [&](int w, int buf) {
        #pragma unroll
        for (int i = 0; i < 8; i++) {
            int c   = t + 256 * i;          // 0..2047
            int op  = c >> 9;               // 0:Ahi 1:Alo 2:Bhi 3:Blo
            int rem = c & 511;
            int row = rem >> 2;
            int q   = rem & 3;
            const __nv_bfloat16* src;
            if (op == 0)      src = Ahi + (size_t)(m0 + row) * Isz + w * 32 + q * 8;
            else if (op == 1) src = Alo + (size_t)(m0 + row) * Isz + w * 32 + q * 8;
            else if (op == 2) src = Whi + (size_t)(n0 + row) * Isz + w * 32 + q * 8;
            else              src = Wlo + (size_t)(n0 + row) * Isz + w * 32 + q * 8;
            cpa16(sb + (uint32_t)buf * XBUF + (uint32_t)op * XHALF
                     + (uint32_t)(row * XROWB + q * 16), src);
        }
        asm volatile("cp.async.commit_group;\n" ::: "memory");
    };

    stage(0, 0);

    #pragma unroll 1
    for (int w = 0; w < 16; w++) {
        if (w < 15) {
            stage(w + 1, (w + 1) & 1);
            asm volatile("cp.async.wait_group 1;\n" ::: "memory");
        } else {
            asm volatile("cp.async.wait_group 0;\n" ::: "memory");
        }
        __syncthreads();

        const uint32_t bufb = sb + (uint32_t)(w & 1) * XBUF;
        const uint32_t* bhi_row[4];
        const uint32_t* blo_row[4];
        #pragma unroll
        for (int ni = 0; ni < 4; ni++) {
            uint32_t r = (uint32_t)((wn + ni * 8 + bg) * XROWB);
            bhi_row[ni] = (const uint32_t*)(xsmem + (w & 1) * XBUF + 2 * XHALF + r);
            blo_row[ni] = (const uint32_t*)(xsmem + (w & 1) * XBUF + 3 * XHALF + r);
        }

        #pragma unroll
        for (int kt = 0; kt < 2; kt++) {
            uint32_t bh0[4], bh1[4], bl0[4], bl1[4];
            #pragma unroll
            for (int ni = 0; ni < 4; ni++) {
                int kw = kt * 8 + btid;
                bh0[ni] = bhi_row[ni][kw];
                bh1[ni] = bhi_row[ni][kw + 4];
                bl0[ni] = blo_row[ni][kw];
                bl1[ni] = blo_row[ni][kw + 4];
            }
            #pragma unroll
            for (int mi = 0; mi < 4; mi++) {
                uint32_t abase = bufb + a_lane_off
                               + (uint32_t)((wm + mi * 16) * XROWB + kt * 32);
                uint32_t ah0, ah1, ah2, ah3, al0, al1, al2, al3;
                ldm4(ah0, ah1, ah2, ah3, abase);
                ldm4(al0, al1, al2, al3, abase + XHALF);
                #pragma unroll
                for (int ni = 0; ni < 4; ni++) {
                    float* d = acc[mi][ni];
                    mma_bf16(d[0], d[1], d[2], d[3], ah0, ah1, ah2, ah3, bh0[ni], bh1[ni]);
                    mma_bf16(d[0], d[1], d[2], d[3], ah0, ah1, ah2, ah3, bl0[ni], bl1[ni]);
                    mma_bf16(d[0], d[1], d[2], d[3], al0, al1, al2, al3, bh0[ni], bh1[ni]);
                }
            }
        }
        __syncthreads();
    }

    // ---- epilogue: add bias, scatter [m][n] -> xg[s][b][n] ----
    #pragma unroll
    for (int ni = 0; ni < 4; ni++) {
        int nn = n0 + wn + ni * 8 + 2 * (lane & 3);
        float b0 = bias[nn], b1 = bias[nn + 1];
        #pragma unroll
        for (int mi = 0; mi < 4; mi++) {
            const float* d = acc[mi][ni];
            int m = m0 + wm + mi * 16 + (lane >> 2);
            int s = m & (Sq - 1), b = m >> 9;
            *(float2*)(xg + (size_t)s * (Bsz * G3) + (size_t)b * G3 + nn) =
                make_float2(d[0] + b0, d[1] + b1);
            int m2 = m + 8;
            int s2 = m2 & (Sq - 1), b2 = m2 >> 9;
            *(float2*)(xg + (size_t)s2 * (Bsz * G3) + (size_t)b2 * G3 + nn) =
                make_float2(d[2] + b0, d[3] + b1);
        }
    }
}

// ---------------------------------------------------------------------------
// Kernel 2: PERSISTENT bf16-split mma.sync GRU scan (proven R9 structure;
// dual accumulator sets + direct hn write added)
// ---------------------------------------------------------------------------
#define OFF_D   0u
#define OFF_W   8192u
#define WROWB   2064u
#define OFF_WLO (OFF_W + 24u * WROWB)
#define OFF_H   107520u
#define HROWB   272u
#define HHALF   (64u * HROWB)
#define HBUF    (2u * HHALF)
#define SCAN_SMEM (OFF_H + 2u * HBUF)

extern __shared__ char smem_raw[];

__global__ __launch_bounds__(512, 1) void gru_scan_kernel(
    const float* __restrict__ xg,
    const float* __restrict__ Whh,
    const float* __restrict__ bhh,
    __nv_bfloat16* __restrict__ hb,
    float* __restrict__ out)
{
    const uint32_t sb = smem_u32(smem_raw);
    const int t    = threadIdx.x;
    const int wid  = t >> 5;
    const int lane = t & 31;
    const int j0   = blockIdx.x * 8;

    // ---- W -> smem as bf16 hi/lo (once) ----
    #pragma unroll
    for (int i = 0; i < 48; i++) {
        int idx = t + 512 * i;
        int r = idx >> 10;
        int k = idx & 1023;
        int gate = r >> 3, jr = r & 7;
        float v = Whh[(size_t)(gate * Hsz + j0 + jr) * Hsz + k];
        __nv_bfloat16 hi = __float2bfloat16(v);
        __nv_bfloat16 lo = __float2bfloat16(v - __bfloat162float(hi));
        *(__nv_bfloat16*)(smem_raw + OFF_W   + r * WROWB + k * 2) = hi;
        *(__nv_bfloat16*)(smem_raw + OFF_WLO + r * WROWB + k * 2) = lo;
    }
    __syncthreads();

    unsigned base = 0;
    if (t == 0) base = *(volatile unsigned*)&g_bar_phase;

    const int nt = wid >> 2;
    const int mt = wid & 3;
    const int sub   = lane >> 3;
    const int a_row = mt * 16 + (lane & 7) + ((sub & 1) << 3);
    const uint32_t a_off = (uint32_t)(a_row * HROWB + ((sub >> 1) << 4));
    const int bg   = lane >> 2;
    const int btid = lane & 3;
    const uint32_t* whi_p = (const uint32_t*)(smem_raw + OFF_W   + (nt * 8 + bg) * WROWB);
    const uint32_t* wlo_p = (const uint32_t*)(smem_raw + OFF_WLO + (nt * 8 + bg) * WROWB);

    float bhr[8], bhz[8], bhn[8];
    if (t < 64) {
        #pragma unroll
        for (int jj = 0; jj < 8; jj++) {
            bhr[jj] = bhh[j0 + jj];
            bhz[jj] = bhh[Hsz + j0 + jj];
            bhn[jj] = bhh[2 * Hsz + j0 + jj];
        }
    }

    float* Dp = (float*)(smem_raw + OFF_D);

    for (int s = 0; s < Sq; s++) {
        const int pin  = s & 1, pout = (s + 1) & 1;
        const __nv_bfloat16* hin_hi = hb + (size_t)pin * 2 * (Bsz * Hsz);
        const __nv_bfloat16* hin_lo = hin_hi + (Bsz * Hsz);
        __nv_bfloat16* hout_hi = hb + (size_t)pout * 2 * (Bsz * Hsz);
        __nv_bfloat16* hout_lo = hout_hi + (Bsz * Hsz);
        const float* xgs = xg + (size_t)s * (Bsz * G3);

        float xr[8], xz[8], xn[8], hp[8];
        if (t < 64) {
            const float* xb = xgs + (size_t)t * G3 + j0;
            float4 v0 = __ldg((const float4*)xb);
            float4 v1 = __ldg((const float4*)(xb + 4));
            xr[0]=v0.x; xr[1]=v0.y; xr[2]=v0.z; xr[3]=v0.w;
            xr[4]=v1.x; xr[5]=v1.y; xr[6]=v1.z; xr[7]=v1.w;
            v0 = __ldg((const float4*)(xb + Hsz));
            v1 = __ldg((const float4*)(xb + Hsz + 4));
            xz[0]=v0.x; xz[1]=v0.y; xz[2]=v0.z; xz[3]=v0.w;
            xz[4]=v1.x; xz[5]=v1.y; xz[6]=v1.z; xz[7]=v1.w;
            v0 = __ldg((const float4*)(xb + 2 * Hsz));
            v1 = __ldg((const float4*)(xb + 2 * Hsz + 4));
            xn[0]=v0.x; xn[1]=v0.y; xn[2]=v0.z; xn[3]=v0.w;
            xn[4]=v1.x; xn[5]=v1.y; xn[6]=v1.z; xn[7]=v1.w;
            uint4 uh = __ldcg((const uint4*)(hin_hi + (size_t)t * Hsz + j0));
            uint4 ul = __ldcg((const uint4*)(hin_lo + (size_t)t * Hsz + j0));
            const __nv_bfloat16* ph = (const __nv_bfloat16*)&uh;
            const __nv_bfloat16* pl = (const __nv_bfloat16*)&ul;
            #pragma unroll
            for (int jj = 0; jj < 8; jj++)
                hp[jj] = __bfloat162float(ph[jj]) + __bfloat162float(pl[jj]);
        }

        float dA[4] = {}, dB[4] = {};    // two accumulator sets

        auto stage = [&](int w) {
            int buf = w & 1;
            #pragma unroll
            for (int i = 0; i < 4; i++) {
                int c    = t + 512 * i;
                int half = c >> 10;
                int rem  = c & 1023;
                int row  = rem >> 4;
                int cq   = rem & 15;
                const char* src = (const char*)(half ? hin_lo : hin_hi)
                                  + row * 2048 + w * 256 + cq * 16;
                cpa16(sb + OFF_H + buf * HBUF + half * HHALF
                         + row * HROWB + cq * 16, src);
            }
            asm volatile("cp.async.commit_group;\n" ::: "memory");
        };

        stage(0);

        #pragma unroll 1
        for (int w = 0; w < 8; w++) {
            if (w < 7) {
                stage(w + 1);
                asm volatile("cp.async.wait_group 1;\n" ::: "memory");
            } else {
                asm volatile("cp.async.wait_group 0;\n" ::: "memory");
            }
            __syncthreads();

            if (wid < 12) {
                const uint32_t abase = sb + OFF_H + (uint32_t)(w & 1) * HBUF + a_off;
                #pragma unroll
                for (int kt = 0; kt < 8; kt++) {
                    float* d = (kt & 1) ? dB : dA;
                    uint32_t ah0, ah1, ah2, ah3, al0, al1, al2, al3;
                    ldm4(ah0, ah1, ah2, ah3, abase + kt * 32);
                    ldm4(al0, al1, al2, al3, abase + HHALF + kt * 32);
                    int kw = (w * 8 + kt) * 8 + btid;
                    uint32_t bh0 = whi_p[kw], bh1 = whi_p[kw + 4];
                    uint32_t bl0 = wlo_p[kw], bl1 = wlo_p[kw + 4];
                    mma_bf16(d[0], d[1], d[2], d[3], ah0, ah1, ah2, ah3, bh0, bh1);
                    mma_bf16(d[0], d[1], d[2], d[3], ah0, ah1, ah2, ah3, bl0, bl1);
                    mma_bf16(d[0], d[1], d[2], d[3], al0, al1, al2, al3, bh0, bh1);
                }
            }
            __syncthreads();
        }

        if (wid < 12) {
            int m  = mt * 16 + (lane >> 2);
            int nc = nt * 8 + 2 * (lane & 3);
            Dp[m * 26 + nc]           = dA[0] + dB[0];
            Dp[m * 26 + nc + 1]       = dA[1] + dB[1];
            Dp[(m + 8) * 26 + nc]     = dA[2] + dB[2];
            Dp[(m + 8) * 26 + nc + 1] = dA[3] + dB[3];
        }
        __syncthreads();

        if (t < 64) {
            __nv_bfloat16 whi[8], wlo[8];
            float hnv[8];
            #pragma unroll
            for (int jj = 0; jj < 8; jj++) {
                float ar = Dp[t * 26 + jj];
                float az = Dp[t * 26 + 8 + jj];
                float an = Dp[t * 26 + 16 + jj];
                float r = 1.f / (1.f + expf(-(xr[jj] + ar + bhr[jj])));
                float z = 1.f / (1.f + expf(-(xz[jj] + az + bhz[jj])));
                float n = tanhf(xn[jj] + r * (an + bhn[jj]));
                float h = (1.f - z) * n + z * hp[jj];
                hnv[jj] = h;
                __nv_bfloat16 hi = __float2bfloat16(h);
                whi[jj] = hi;
                wlo[jj] = __float2bfloat16(h - __bfloat162float(hi));
            }
            float* op = out + (size_t)t * Sq * Hsz + (size_t)s * Hsz + j0;
            *(float4*)op       = make_float4(hnv[0], hnv[1], hnv[2], hnv[3]);
            *(float4*)(op + 4) = make_float4(hnv[4], hnv[5], hnv[6], hnv[7]);
            *(uint4*)(hout_hi + (size_t)t * Hsz + j0) = *(uint4*)whi;
            *(uint4*)(hout_lo + (size_t)t * Hsz + j0) = *(uint4*)wlo;
            if (s == Sq - 1) {
                float* hn = out + (size_t)Bsz * Sq * Hsz + (size_t)t * Hsz + j0;
                *(float4*)hn       = make_float4(hnv[0], hnv[1], hnv[2], hnv[3]);
                *(float4*)(hn + 4) = make_float4(hnv[4], hnv[5], hnv[6], hnv[7]);
            }
        }

        __syncthreads();
        if (t == 0 && s + 1 < Sq) {
            __threadfence();
            unsigned arr = atomicAdd(&g_bar_count, 1);
            if (arr == gridDim.x - 1) {
                atomicExch(&g_bar_count, 0);
                __threadfence();
                atomicAdd(&g_bar_phase, 1);
            } else {
                unsigned target = (unsigned)(s + 1);
                unsigned spins = 0;
                while ((unsigned)(*(volatile unsigned*)&g_bar_phase - base) < target) {
                    if (++spins > 200000000u) break;   // fail loud, not hung
                }
                __threadfence();
            }
        }
        __syncthreads();
    }
}

// ---------------------------------------------------------------------------
// kernel_launch (graph-capturable: kernel launches only)
// ---------------------------------------------------------------------------
extern "C" void kernel_launch(void* const* d_in, const int* in_sizes, int n_in,
                              void* d_out, int out_size)
{
    const float* inputs = (const float*)d_in[0];
    const float* h0     = (const float*)d_in[1];
    const float* Wih    = (const float*)d_in[2];
    const float* Whh    = (const float*)d_in[3];
    const float* bih    = (const float*)d_in[4];
    const float* bhh    = (const float*)d_in[5];
    float* out = (float*)d_out;

    float* xg = nullptr;
    __nv_bfloat16 *hb = nullptr, *ahi = nullptr, *alo = nullptr,
                  *whi = nullptr, *wlo = nullptr;
    cudaGetSymbolAddress((void**)&xg,  g_xg);
    cudaGetSymbolAddress((void**)&hb,  g_hb);
    cudaGetSymbolAddress((void**)&ahi, g_Ahi);
    cudaGetSymbolAddress((void**)&alo, g_Alo);
    cudaGetSymbolAddress((void**)&whi, g_Whi);
    cudaGetSymbolAddress((void**)&wlo, g_Wlo);

    cudaFuncSetAttribute(gru_scan_kernel,
                         cudaFuncAttributeMaxDynamicSharedMemorySize, SCAN_SMEM);
    cudaFuncSetAttribute(xgemm_mma_kernel,
                         cudaFuncAttributeMaxDynamicSharedMemorySize, XGEMM_SMEM);

    // Phase A: split inputs/Wih to bf16 hi/lo, then HMMA input-projection GEMM
    split_kernel<<<(int)((size_t)Bsz * Sq * Isz / 4 / 256), 256>>>(inputs, ahi, alo);
    split_kernel<<<(int)((size_t)G3 * Isz / 4 / 256), 256>>>(Wih, whi, wlo);
    h0_prep_kernel<<<(Bsz * Hsz) / 256, 256>>>(h0, hb, hb + Bsz * Hsz);

    dim3 ggrid(G3 / 128, (Bsz * Sq) / 128);   // (24, 256)
    xgemm_mma_kernel<<<ggrid, 256, XGEMM_SMEM>>>(ahi, alo, whi, wlo, bih, xg);

    // Phase B: whole scan in ONE persistent mma.sync kernel (writes hn too)
    gru_scan_kernel<<<128, 512, SCAN_SMEM>>>(xg, Whh, bhh, hb, out);
}